// round 10
// baseline (speedup 1.0000x reference)
#include <cuda_runtime.h>
#include <cuda_fp16.h>
#include <math.h>

#define BATCH 4
#define CH    128
#define N_    4096
#define EPSV  2.220446049250313e-16f
#define SCALE2 144.26950408889634f   // 100 * log2(e)

// ---------------------------------------------------------------------------
// Device scratch
// ---------------------------------------------------------------------------
__device__ float g_xbar[2 * BATCH * CH];
__device__ float g_theta[BATCH * CH * N_];        // keys    [b][c][m]
__device__ float g_phi[BATCH * CH * N_];          // queries [b][c][n]
__device__ uint4 g_Qpk[BATCH * 32 * 4096];        // Q A-frags: [0,2048) hi, [2048,4096) lo per blk
__device__ uint4 g_Kpk[BATCH * 64 * 2048];        // K B-frags (b0h,b1h,b0l,b1l) per 64-key blk
__device__ uint4 g_Vpk[BATCH * 64 * 2048];        // V B-frags (vh01,vh89,vl01,vl89) per blk

__device__ __forceinline__ void mma_f16(float c[4],
                                        unsigned int a0, unsigned int a1,
                                        unsigned int a2, unsigned int a3,
                                        unsigned int b0, unsigned int b1) {
    asm volatile("mma.sync.aligned.m16n8k16.row.col.f32.f16.f16.f32 "
                 "{%0,%1,%2,%3}, {%4,%5,%6,%7}, {%8,%9}, {%0,%1,%2,%3};\n"
                 : "+f"(c[0]), "+f"(c[1]), "+f"(c[2]), "+f"(c[3])
                 : "r"(a0), "r"(a1), "r"(a2), "r"(a3), "r"(b0), "r"(b1));
}

__device__ __forceinline__ unsigned int h2u(__half2 h) {
    return *reinterpret_cast<unsigned int*>(&h);
}

__device__ __forceinline__ unsigned int pack_hi(float a, float b) {
    return h2u(__halves2half2(__float2half_rn(a), __float2half_rn(b)));
}
// lo residual of f16 split
__device__ __forceinline__ unsigned int pack_lo(float a, float b) {
    __half ha = __float2half_rn(a), hb = __float2half_rn(b);
    return h2u(__halves2half2(__float2half_rn(a - __half2float(ha)),
                              __float2half_rn(b - __half2float(hb))));
}

__device__ __forceinline__ void cpasync16(void* s, const void* g) {
    unsigned int saddr = (unsigned int)__cvta_generic_to_shared(s);
    asm volatile("cp.async.cg.shared.global [%0], [%1], 16;\n" :: "r"(saddr), "l"(g));
}

// ---------------------------------------------------------------------------
// K0: spatial means
// ---------------------------------------------------------------------------
__global__ void k_means(const float* __restrict__ m_in, const float* __restrict__ rs) {
    int row   = blockIdx.x;
    int which = row >> 9;
    int bc    = row & 511;
    const float* src = which ? m_in : rs;
    const float* p = src + (size_t)bc * N_;

    float s = 0.f;
    for (int i = threadIdx.x; i < N_; i += 256) s += p[i];

    __shared__ float sh[256];
    sh[threadIdx.x] = s;
    __syncthreads();
    for (int off = 128; off > 0; off >>= 1) {
        if (threadIdx.x < off) sh[threadIdx.x] += sh[threadIdx.x + off];
        __syncthreads();
    }
    if (threadIdx.x == 0) g_xbar[which * 512 + bc] = sh[0] * (1.0f / N_);
}

// ---------------------------------------------------------------------------
// K1: projection + mean-center + L2-normalize (bias cancels under centering)
// ---------------------------------------------------------------------------
__global__ void k_proj(const float* __restrict__ m_in, const float* __restrict__ rs,
                       const float* __restrict__ theta_w, const float* __restrict__ phi_w) {
    int tile  = blockIdx.x;
    int b     = blockIdx.y;
    int which = blockIdx.z;
    const float* X = which ? m_in : rs;
    const float* W = which ? phi_w : theta_w;
    float* OUT     = which ? g_phi : g_theta;
    const float* xbar = &g_xbar[which * 512 + b * CH];

    int o  = threadIdx.x;
    int n0 = tile * 16;

    __shared__ float Ws[128 * 33];
    __shared__ float xs[32 * 16];
    __shared__ float sq[128 * 17];

    float acc[16];
#pragma unroll
    for (int j = 0; j < 16; j++) acc[j] = 0.f;

    for (int c0 = 0; c0 < CH; c0 += 32) {
        for (int i = threadIdx.x; i < 128 * 32; i += 128) {
            int oo = i >> 5, cc = i & 31;
            Ws[oo * 33 + cc] = W[oo * CH + c0 + cc];
        }
        for (int i = threadIdx.x; i < 32 * 16; i += 128) {
            int cc = i >> 4;
            int j  = i & 15;
            int c  = c0 + cc;
            xs[i] = X[((size_t)(b * CH + c)) * N_ + n0 + j] - xbar[c];
        }
        __syncthreads();
#pragma unroll 8
        for (int cc = 0; cc < 32; cc++) {
            float w = Ws[o * 33 + cc];
#pragma unroll
            for (int j = 0; j < 16; j++) acc[j] += w * xs[cc * 16 + j];
        }
        __syncthreads();
    }

#pragma unroll
    for (int j = 0; j < 16; j++) sq[o * 17 + j] = acc[j] * acc[j];
    for (int off = 64; off > 0; off >>= 1) {
        __syncthreads();
        if (o < off) {
#pragma unroll
            for (int j = 0; j < 16; j++) sq[o * 17 + j] += sq[(o + off) * 17 + j];
        }
    }
    __syncthreads();

#pragma unroll
    for (int j = 0; j < 16; j++) {
        float norm = sqrtf(sq[j]) + EPSV;
        OUT[((size_t)(b * CH + o)) * N_ + n0 + j] = acc[j] / norm;
    }
}

// ---------------------------------------------------------------------------
// Pack Q (phi) into m16n8k16 A-frag order, f16 hi + f16 lo.
// Frag (ks in 8, wt in 8, lane): a0=(r=16wt+g, c=16ks+2l..+1), a1=rows+8,
// a2=cols+8, a3=both+8.  grid (32, BATCH), 256 threads, dyn smem 67584B.
// ---------------------------------------------------------------------------
__global__ void k_packQ() {
    extern __shared__ float Qs[];   // [c][r] stride 132
    int blk = blockIdx.x, b = blockIdx.y;
    int n0 = blk * 128;

    for (int i = threadIdx.x; i < 16384; i += 256) {
        int c = i >> 7, r = i & 127;
        Qs[c * 132 + r] = g_phi[((size_t)(b * CH + c)) * N_ + n0 + r];
    }
    __syncthreads();

    uint4* dst = g_Qpk + ((size_t)(b * 32 + blk)) * 4096;
    for (int o = threadIdx.x; o < 2048; o += 256) {
        int lane = o & 31, wt = (o >> 5) & 7, ks = o >> 8;
        int g = lane >> 2, l = lane & 3;
        int r = 16 * wt + g, c = 16 * ks + 2 * l;
        float q00 = Qs[c * 132 + r],           q01 = Qs[(c + 1) * 132 + r];
        float q10 = Qs[c * 132 + r + 8],       q11 = Qs[(c + 1) * 132 + r + 8];
        float q20 = Qs[(c + 8) * 132 + r],     q21 = Qs[(c + 9) * 132 + r];
        float q30 = Qs[(c + 8) * 132 + r + 8], q31 = Qs[(c + 9) * 132 + r + 8];
        uint4 hi, lo;
        hi.x = pack_hi(q00, q01); lo.x = pack_lo(q00, q01);
        hi.y = pack_hi(q10, q11); lo.y = pack_lo(q10, q11);
        hi.z = pack_hi(q20, q21); lo.z = pack_lo(q20, q21);
        hi.w = pack_hi(q30, q31); lo.w = pack_lo(q30, q31);
        dst[o] = hi;
        dst[2048 + o] = lo;
    }
}

// ---------------------------------------------------------------------------
// Pack K (theta) into m16n8k16 B-frag order, uint4 = (b0h,b1h,b0l,b1l).
// ---------------------------------------------------------------------------
__global__ void k_packK() {
    __shared__ float Ks[128 * 68];  // [c][m]
    int kb = blockIdx.x, b = blockIdx.y;
    int m0 = kb * 64;

    for (int i = threadIdx.x; i < 8192; i += 256) {
        int c = i >> 6, m = i & 63;
        Ks[c * 68 + m] = g_theta[((size_t)(b * CH + c)) * N_ + m0 + m];
    }
    __syncthreads();

    uint4* dst = g_Kpk + ((size_t)(b * 64 + kb)) * 2048;
    for (int o = threadIdx.x; o < 2048; o += 256) {
        int lane = o & 31, nt = (o >> 5) & 7, ks = o >> 8;
        int g = lane >> 2, l = lane & 3;
        int c = 16 * ks + 2 * l, m = 8 * nt + g;
        float k00 = Ks[c * 68 + m],       k01 = Ks[(c + 1) * 68 + m];
        float k10 = Ks[(c + 8) * 68 + m], k11 = Ks[(c + 9) * 68 + m];
        uint4 outv;
        outv.x = pack_hi(k00, k01);
        outv.y = pack_hi(k10, k11);
        outv.z = pack_lo(k00, k01);
        outv.w = pack_lo(k10, k11);
        dst[o] = outv;
    }
}

// ---------------------------------------------------------------------------
// Pack V (rs) into m16n8k16 B-frag order, f16 hi + f16 lo.
// ---------------------------------------------------------------------------
__global__ void k_packV(const float* __restrict__ rs) {
    __shared__ float Vt[128 * 68];
    int kb = blockIdx.x, b = blockIdx.y;
    int m0 = kb * 64;

    for (int i = threadIdx.x; i < 2048; i += 256) {
        int c = i >> 4, mq = (i & 15) << 2;
        float4 v = *(const float4*)(rs + ((size_t)(b * CH + c)) * N_ + m0 + mq);
        *(float4*)(Vt + c * 68 + mq) = v;
    }
    __syncthreads();

    uint4* dst = g_Vpk + ((size_t)(b * 64 + kb)) * 2048;
    for (int o = threadIdx.x; o < 2048; o += 256) {
        int lane = o & 31, ct = (o >> 5) & 15, kt = o >> 9;
        int g = lane >> 2, l = lane & 3;
        int c = 8 * ct + g;
        int m = 16 * kt + 2 * l;
        float v0 = Vt[c * 68 + m],     v1 = Vt[c * 68 + m + 1];
        float v8 = Vt[c * 68 + m + 8], v9 = Vt[c * 68 + m + 9];
        uint4 outv;
        outv.x = pack_hi(v0, v1);
        outv.y = pack_hi(v8, v9);
        outv.z = pack_lo(v0, v1);
        outv.w = pack_lo(v8, v9);
        dst[o] = outv;
    }
}

// ---------------------------------------------------------------------------
// K2: flash attention v6. 512 threads = 16 warps.
// Warp w: wt = w&7 owns rows 16wt..+15; grp = w>>3 owns keys [32*grp, +32)
// of each 64-key tile. S: 3x f16 m16n8k16. PV: 3x f16 m16n8k16.
// K/V double-buffered via cp.async. Final cross-group flash merge via smem.
// ---------------------------------------------------------------------------
__global__ void __launch_bounds__(512, 1)
k_attn(float* __restrict__ out) {
    extern __shared__ float sm[];
    uint4* Qf = (uint4*)sm;                  // 4096 uint4: [0,2048) hi, [2048,4096) lo

    int b    = blockIdx.y;
    int n0   = blockIdx.x << 7;
    int tid  = threadIdx.x;
    int lane = tid & 31, w = tid >> 5;
    int wt = w & 7, grp = w >> 3;
    int ntb = grp << 2;                      // nt base
    int g = lane >> 2, l = lane & 3;

    // load persistent Q fragments
    {
        const uint4* qsrc = g_Qpk + ((size_t)(b * 32 + blockIdx.x)) * 4096;
        for (int i = tid; i < 4096; i += 512) Qf[i] = qsrc[i];
    }

    // prologue: async load tile 0 into buffer 0
    {
        uint4* bd = (uint4*)(sm + 16384);
        const uint4* ksrc = g_Kpk + ((size_t)(b * 64 + 0)) * 2048;
        for (int i = tid; i < 2048; i += 512) cpasync16(bd + i, ksrc + i);
        const uint4* vsrc = g_Vpk + ((size_t)(b * 64 + 0)) * 2048;
        for (int i = tid; i < 2048; i += 512) cpasync16(bd + 2048 + i, vsrc + i);
        asm volatile("cp.async.commit_group;\n" ::);
    }

    float O[16][4];
#pragma unroll
    for (int ct = 0; ct < 16; ct++)
#pragma unroll
        for (int j = 0; j < 4; j++) O[ct][j] = 0.f;
    float mi[2] = {-INFINITY, -INFINITY};
    float li[2] = {0.f, 0.f};

    for (int kb = 0; kb < 64; kb++) {
        int cur = kb & 1;
        uint4* Kbuf = (uint4*)(sm + 16384 + cur * 16384);
        uint4* Vbuf = Kbuf + 2048;

        if (kb < 63) {
            uint4* bd = (uint4*)(sm + 16384 + (1 - cur) * 16384);
            const uint4* ksrc = g_Kpk + ((size_t)(b * 64 + kb + 1)) * 2048;
            for (int i = tid; i < 2048; i += 512) cpasync16(bd + i, ksrc + i);
            const uint4* vsrc = g_Vpk + ((size_t)(b * 64 + kb + 1)) * 2048;
            for (int i = tid; i < 2048; i += 512) cpasync16(bd + 2048 + i, vsrc + i);
            asm volatile("cp.async.commit_group;\n" ::);
            asm volatile("cp.async.wait_group 1;\n" ::);
        } else {
            asm volatile("cp.async.wait_group 0;\n" ::);
        }
        __syncthreads();

        // ---- S = Q^T K over this group's 32 keys : 3x f16 mma ----
        float S[4][4];
#pragma unroll
        for (int nt = 0; nt < 4; nt++)
#pragma unroll
            for (int j = 0; j < 4; j++) S[nt][j] = 0.f;

#pragma unroll
        for (int ks = 0; ks < 8; ks++) {
            int qi = (ks * 8 + wt) * 32 + lane;
            uint4 qh = Qf[qi];
            uint4 ql = Qf[2048 + qi];
#pragma unroll
            for (int nt4 = 0; nt4 < 4; nt4++) {
                uint4 kf = Kbuf[(ks * 8 + ntb + nt4) * 32 + lane];
                mma_f16(S[nt4], qh.x, qh.y, qh.z, qh.w, kf.x, kf.y);
                mma_f16(S[nt4], ql.x, ql.y, ql.z, ql.w, kf.x, kf.y);
                mma_f16(S[nt4], qh.x, qh.y, qh.z, qh.w, kf.z, kf.w);
            }
        }

        // ---- warp-local online softmax over 32 keys; P overwrites S ----
#pragma unroll
        for (int hb = 0; hb < 2; hb++) {
            float vmax = -INFINITY;
#pragma unroll
            for (int nt = 0; nt < 4; nt++)
                vmax = fmaxf(vmax, fmaxf(S[nt][2 * hb], S[nt][2 * hb + 1]));
            vmax = fmaxf(vmax, __shfl_xor_sync(0xffffffffu, vmax, 1));
            vmax = fmaxf(vmax, __shfl_xor_sync(0xffffffffu, vmax, 2));
            float mnew  = fmaxf(mi[hb], vmax);
            float alpha = exp2f((mi[hb] - mnew) * SCALE2);
            mi[hb] = mnew;

            float rs_ = 0.f;
#pragma unroll
            for (int nt = 0; nt < 4; nt++) {
                float p0 = exp2f((S[nt][2 * hb]     - mnew) * SCALE2);
                float p1 = exp2f((S[nt][2 * hb + 1] - mnew) * SCALE2);
                S[nt][2 * hb]     = p0;
                S[nt][2 * hb + 1] = p1;
                rs_ += p0 + p1;
            }
            rs_ += __shfl_xor_sync(0xffffffffu, rs_, 1);
            rs_ += __shfl_xor_sync(0xffffffffu, rs_, 2);
            li[hb] = li[hb] * alpha + rs_;

#pragma unroll
            for (int ct = 0; ct < 16; ct++) {
                O[ct][2 * hb]     *= alpha;
                O[ct][2 * hb + 1] *= alpha;
            }
        }

        // ---- PV over this group's 2 kt blocks : 3x f16 mma ----
#pragma unroll
        for (int kt2 = 0; kt2 < 2; kt2++) {
            unsigned int Pha[4], Pla[4];
#pragma unroll
            for (int hf2 = 0; hf2 < 2; hf2++) {
                int nt = 2 * kt2 + hf2;
#pragma unroll
                for (int hb = 0; hb < 2; hb++) {
                    float p0 = S[nt][2 * hb], p1 = S[nt][2 * hb + 1];
                    Pha[hf2 * 2 + hb] = pack_hi(p0, p1);
                    Pla[hf2 * 2 + hb] = pack_lo(p0, p1);
                }
            }
            int kt = 2 * grp + kt2;
#pragma unroll
            for (int ct = 0; ct < 16; ct++) {
                uint4 vf = Vbuf[(kt * 16 + ct) * 32 + lane];
                mma_f16(O[ct], Pha[0], Pha[1], Pha[2], Pha[3], vf.x, vf.y);
                mma_f16(O[ct], Pla[0], Pla[1], Pla[2], Pla[3], vf.x, vf.y);
                mma_f16(O[ct], Pha[0], Pha[1], Pha[2], Pha[3], vf.z, vf.w);
            }
        }
        __syncthreads();
    }

    // ---- cross-group flash merge via smem (aliases buffers) ----
    float* MG = sm + 16384;   // 68 * 512 floats
    if (grp == 1) {
        int slot = tid - 256;
#pragma unroll
        for (int ct = 0; ct < 16; ct++)
#pragma unroll
            for (int j = 0; j < 4; j++)
                MG[(ct * 4 + j) * 512 + slot] = O[ct][j];
#pragma unroll
        for (int hb = 0; hb < 2; hb++) {
            MG[(64 + hb) * 512 + slot] = mi[hb];
            MG[(66 + hb) * 512 + slot] = li[hb];
        }
    }
    __syncthreads();

    if (grp == 0) {
        float* yout = out;
        float* loc  = out + (size_t)BATCH * CH * N_;
#pragma unroll
        for (int hb = 0; hb < 2; hb++) {
            float m1 = MG[(64 + hb) * 512 + tid];
            float l1 = MG[(66 + hb) * 512 + tid];
            float m  = fmaxf(mi[hb], m1);
            float a0 = exp2f((mi[hb] - m) * SCALE2);
            float a1 = exp2f((m1 - m) * SCALE2);
            float lt = li[hb] * a0 + l1 * a1;
            float inv = 1.0f / lt;
            float sc  = m * inv;
            int   r   = n0 + 16 * wt + g + 8 * hb;
#pragma unroll
            for (int ct = 0; ct < 16; ct++) {
                float o0 = O[ct][2 * hb]     * a0 + MG[(ct * 4 + 2 * hb) * 512 + tid]     * a1;
                float o1 = O[ct][2 * hb + 1] * a0 + MG[(ct * 4 + 2 * hb + 1) * 512 + tid] * a1;
                int c0 = 8 * ct + 2 * l;
                yout[((size_t)(b * CH + c0)) * N_ + r]     = o0 * sc;
                yout[((size_t)(b * CH + c0 + 1)) * N_ + r] = o1 * sc;
            }
            if (l == 0) loc[(size_t)b * N_ + r] = inv;
        }
    }
}

// ---------------------------------------------------------------------------
extern "C" void kernel_launch(void* const* d_in, const int* in_sizes, int n_in,
                              void* d_out, int out_size) {
    const float* m_in = (const float*)d_in[0];
    const float* rs   = (const float*)d_in[1];
    const float* thw  = (const float*)d_in[2];
    const float* phw  = (const float*)d_in[4];
    float* out = (float*)d_out;

    k_means<<<1024, 256>>>(m_in, rs);
    k_proj<<<dim3(N_ / 16, BATCH, 2), 128>>>(m_in, rs, thw, phw);

    cudaFuncSetAttribute(k_packQ, cudaFuncAttributeMaxDynamicSharedMemorySize, 132 * 128 * 4);
    k_packQ<<<dim3(32, BATCH), 256, 132 * 128 * 4>>>();
    k_packK<<<dim3(64, BATCH), 256>>>();
    k_packV<<<dim3(64, BATCH), 256>>>(rs);

    size_t smem = (size_t)51200 * sizeof(float);   // 200 KB
    cudaFuncSetAttribute(k_attn, cudaFuncAttributeMaxDynamicSharedMemorySize, (int)smem);
    k_attn<<<dim3(N_ / 128, BATCH), 512, smem>>>(out);
}

// round 11
// speedup vs baseline: 1.1167x; 1.1167x over previous
#include <cuda_runtime.h>
#include <cuda_fp16.h>
#include <math.h>

#define BATCH 4
#define CH    128
#define N_    4096
#define EPSV  2.220446049250313e-16f
#define SCALE2 144.26950408889634f   // 100 * log2(e)

// ---------------------------------------------------------------------------
// Device scratch
// ---------------------------------------------------------------------------
__device__ float g_xbar[2 * BATCH * CH];
__device__ float g_theta[BATCH * CH * N_];        // keys    [b][c][m]
__device__ float g_phi[BATCH * CH * N_];          // queries [b][c][n]
__device__ uint4 g_Qpk[BATCH * 32 * 4096];        // Q A-frags: [0,2048) hi, [2048,4096) lo per blk
__device__ uint4 g_Kpk[BATCH * 64 * 2048];        // K B-frags (b0h,b1h,b0l,b1l) per 64-key blk
__device__ uint2 g_Vpk[BATCH * 64 * 2048];        // V B-frags hi-only (vh01,vh89) per blk

__device__ __forceinline__ void mma_f16(float c[4],
                                        unsigned int a0, unsigned int a1,
                                        unsigned int a2, unsigned int a3,
                                        unsigned int b0, unsigned int b1) {
    asm volatile("mma.sync.aligned.m16n8k16.row.col.f32.f16.f16.f32 "
                 "{%0,%1,%2,%3}, {%4,%5,%6,%7}, {%8,%9}, {%0,%1,%2,%3};\n"
                 : "+f"(c[0]), "+f"(c[1]), "+f"(c[2]), "+f"(c[3])
                 : "r"(a0), "r"(a1), "r"(a2), "r"(a3), "r"(b0), "r"(b1));
}

__device__ __forceinline__ unsigned int h2u(__half2 h) {
    return *reinterpret_cast<unsigned int*>(&h);
}

__device__ __forceinline__ unsigned int pack_hi(float a, float b) {
    return h2u(__halves2half2(__float2half_rn(a), __float2half_rn(b)));
}
// lo residual of f16 split
__device__ __forceinline__ unsigned int pack_lo(float a, float b) {
    __half ha = __float2half_rn(a), hb = __float2half_rn(b);
    return h2u(__halves2half2(__float2half_rn(a - __half2float(ha)),
                              __float2half_rn(b - __half2float(hb))));
}

__device__ __forceinline__ void cpasync16(void* s, const void* g) {
    unsigned int saddr = (unsigned int)__cvta_generic_to_shared(s);
    asm volatile("cp.async.cg.shared.global [%0], [%1], 16;\n" :: "r"(saddr), "l"(g));
}

// ---------------------------------------------------------------------------
// K0: spatial means
// ---------------------------------------------------------------------------
__global__ void k_means(const float* __restrict__ m_in, const float* __restrict__ rs) {
    int row   = blockIdx.x;
    int which = row >> 9;
    int bc    = row & 511;
    const float* src = which ? m_in : rs;
    const float* p = src + (size_t)bc * N_;

    float s = 0.f;
    for (int i = threadIdx.x; i < N_; i += 256) s += p[i];

    __shared__ float sh[256];
    sh[threadIdx.x] = s;
    __syncthreads();
    for (int off = 128; off > 0; off >>= 1) {
        if (threadIdx.x < off) sh[threadIdx.x] += sh[threadIdx.x + off];
        __syncthreads();
    }
    if (threadIdx.x == 0) g_xbar[which * 512 + bc] = sh[0] * (1.0f / N_);
}

// ---------------------------------------------------------------------------
// K1: projection + mean-center + L2-normalize (bias cancels under centering)
// ---------------------------------------------------------------------------
__global__ void k_proj(const float* __restrict__ m_in, const float* __restrict__ rs,
                       const float* __restrict__ theta_w, const float* __restrict__ phi_w) {
    int tile  = blockIdx.x;
    int b     = blockIdx.y;
    int which = blockIdx.z;
    const float* X = which ? m_in : rs;
    const float* W = which ? phi_w : theta_w;
    float* OUT     = which ? g_phi : g_theta;
    const float* xbar = &g_xbar[which * 512 + b * CH];

    int o  = threadIdx.x;
    int n0 = tile * 16;

    __shared__ float Ws[128 * 33];
    __shared__ float xs[32 * 16];
    __shared__ float sq[128 * 17];

    float acc[16];
#pragma unroll
    for (int j = 0; j < 16; j++) acc[j] = 0.f;

    for (int c0 = 0; c0 < CH; c0 += 32) {
        for (int i = threadIdx.x; i < 128 * 32; i += 128) {
            int oo = i >> 5, cc = i & 31;
            Ws[oo * 33 + cc] = W[oo * CH + c0 + cc];
        }
        for (int i = threadIdx.x; i < 32 * 16; i += 128) {
            int cc = i >> 4;
            int j  = i & 15;
            int c  = c0 + cc;
            xs[i] = X[((size_t)(b * CH + c)) * N_ + n0 + j] - xbar[c];
        }
        __syncthreads();
#pragma unroll 8
        for (int cc = 0; cc < 32; cc++) {
            float w = Ws[o * 33 + cc];
#pragma unroll
            for (int j = 0; j < 16; j++) acc[j] += w * xs[cc * 16 + j];
        }
        __syncthreads();
    }

#pragma unroll
    for (int j = 0; j < 16; j++) sq[o * 17 + j] = acc[j] * acc[j];
    for (int off = 64; off > 0; off >>= 1) {
        __syncthreads();
        if (o < off) {
#pragma unroll
            for (int j = 0; j < 16; j++) sq[o * 17 + j] += sq[(o + off) * 17 + j];
        }
    }
    __syncthreads();

#pragma unroll
    for (int j = 0; j < 16; j++) {
        float norm = sqrtf(sq[j]) + EPSV;
        OUT[((size_t)(b * CH + o)) * N_ + n0 + j] = acc[j] / norm;
    }
}

// ---------------------------------------------------------------------------
// Pack Q (phi) into m16n8k16 A-frag order, f16 hi + f16 lo.
// ---------------------------------------------------------------------------
__global__ void k_packQ() {
    extern __shared__ float Qs[];   // [c][r] stride 132
    int blk = blockIdx.x, b = blockIdx.y;
    int n0 = blk * 128;

    for (int i = threadIdx.x; i < 16384; i += 256) {
        int c = i >> 7, r = i & 127;
        Qs[c * 132 + r] = g_phi[((size_t)(b * CH + c)) * N_ + n0 + r];
    }
    __syncthreads();

    uint4* dst = g_Qpk + ((size_t)(b * 32 + blk)) * 4096;
    for (int o = threadIdx.x; o < 2048; o += 256) {
        int lane = o & 31, wt = (o >> 5) & 7, ks = o >> 8;
        int g = lane >> 2, l = lane & 3;
        int r = 16 * wt + g, c = 16 * ks + 2 * l;
        float q00 = Qs[c * 132 + r],           q01 = Qs[(c + 1) * 132 + r];
        float q10 = Qs[c * 132 + r + 8],       q11 = Qs[(c + 1) * 132 + r + 8];
        float q20 = Qs[(c + 8) * 132 + r],     q21 = Qs[(c + 9) * 132 + r];
        float q30 = Qs[(c + 8) * 132 + r + 8], q31 = Qs[(c + 9) * 132 + r + 8];
        uint4 hi, lo;
        hi.x = pack_hi(q00, q01); lo.x = pack_lo(q00, q01);
        hi.y = pack_hi(q10, q11); lo.y = pack_lo(q10, q11);
        hi.z = pack_hi(q20, q21); lo.z = pack_lo(q20, q21);
        hi.w = pack_hi(q30, q31); lo.w = pack_lo(q30, q31);
        dst[o] = hi;
        dst[2048 + o] = lo;
    }
}

// ---------------------------------------------------------------------------
// Pack K (theta) into m16n8k16 B-frag order, uint4 = (b0h,b1h,b0l,b1l).
// ---------------------------------------------------------------------------
__global__ void k_packK() {
    __shared__ float Ks[128 * 68];  // [c][m]
    int kb = blockIdx.x, b = blockIdx.y;
    int m0 = kb * 64;

    for (int i = threadIdx.x; i < 8192; i += 256) {
        int c = i >> 6, m = i & 63;
        Ks[c * 68 + m] = g_theta[((size_t)(b * CH + c)) * N_ + m0 + m];
    }
    __syncthreads();

    uint4* dst = g_Kpk + ((size_t)(b * 64 + kb)) * 2048;
    for (int o = threadIdx.x; o < 2048; o += 256) {
        int lane = o & 31, nt = (o >> 5) & 7, ks = o >> 8;
        int g = lane >> 2, l = lane & 3;
        int c = 16 * ks + 2 * l, m = 8 * nt + g;
        float k00 = Ks[c * 68 + m],       k01 = Ks[(c + 1) * 68 + m];
        float k10 = Ks[(c + 8) * 68 + m], k11 = Ks[(c + 9) * 68 + m];
        uint4 outv;
        outv.x = pack_hi(k00, k01);
        outv.y = pack_hi(k10, k11);
        outv.z = pack_lo(k00, k01);
        outv.w = pack_lo(k10, k11);
        dst[o] = outv;
    }
}

// ---------------------------------------------------------------------------
// Pack V (rs) into m16n8k16 B-frag order, f16 hi only (uint2 per frag).
// ---------------------------------------------------------------------------
__global__ void k_packV(const float* __restrict__ rs) {
    __shared__ float Vt[128 * 68];
    int kb = blockIdx.x, b = blockIdx.y;
    int m0 = kb * 64;

    for (int i = threadIdx.x; i < 2048; i += 256) {
        int c = i >> 4, mq = (i & 15) << 2;
        float4 v = *(const float4*)(rs + ((size_t)(b * CH + c)) * N_ + m0 + mq);
        *(float4*)(Vt + c * 68 + mq) = v;
    }
    __syncthreads();

    uint2* dst = g_Vpk + ((size_t)(b * 64 + kb)) * 2048;
    for (int o = threadIdx.x; o < 2048; o += 256) {
        int lane = o & 31, ct = (o >> 5) & 15, kt = o >> 9;
        int g = lane >> 2, l = lane & 3;
        int c = 8 * ct + g;
        int m = 16 * kt + 2 * l;
        uint2 outv;
        outv.x = pack_hi(Vt[c * 68 + m],     Vt[c * 68 + m + 1]);
        outv.y = pack_hi(Vt[c * 68 + m + 8], Vt[c * 68 + m + 9]);
        dst[o] = outv;
    }
}

// ---------------------------------------------------------------------------
// K2: flash attention v7. 512 threads = 16 warps.
// Warp w: wt = w&7 owns rows 16wt..+15; grp = w>>3 owns keys [32*grp, +32).
// S: 3x f16 m16n8k16 (hi/lo). PV: 2x f16 m16n8k16 (Ph*Vh + Pl*Vh).
// K/V double-buffered via cp.async. Buffer = K 8192 floats + V 4096 floats.
// ---------------------------------------------------------------------------
#define BUF_FLOATS 12288

__global__ void __launch_bounds__(512, 1)
k_attn(float* __restrict__ out) {
    extern __shared__ float sm[];
    uint4* Qf = (uint4*)sm;                  // 4096 uint4: [0,2048) hi, [2048,4096) lo

    int b    = blockIdx.y;
    int n0   = blockIdx.x << 7;
    int tid  = threadIdx.x;
    int lane = tid & 31, w = tid >> 5;
    int wt = w & 7, grp = w >> 3;
    int ntb = grp << 2;                      // nt base
    int g = lane >> 2, l = lane & 3;

    // load persistent Q fragments
    {
        const uint4* qsrc = g_Qpk + ((size_t)(b * 32 + blockIdx.x)) * 4096;
        for (int i = tid; i < 4096; i += 512) Qf[i] = qsrc[i];
    }

    // prologue: async load tile 0 into buffer 0
    {
        uint4* kd = (uint4*)(sm + 16384);
        const uint4* ksrc = g_Kpk + ((size_t)(b * 64 + 0)) * 2048;
        for (int i = tid; i < 2048; i += 512) cpasync16(kd + i, ksrc + i);
        uint4* vd = (uint4*)(sm + 16384 + 8192);
        const uint4* vsrc = (const uint4*)(g_Vpk + ((size_t)(b * 64 + 0)) * 2048);
        for (int i = tid; i < 1024; i += 512) cpasync16(vd + i, vsrc + i);
        asm volatile("cp.async.commit_group;\n" ::);
    }

    float O[16][4];
#pragma unroll
    for (int ct = 0; ct < 16; ct++)
#pragma unroll
        for (int j = 0; j < 4; j++) O[ct][j] = 0.f;
    float mi[2] = {-INFINITY, -INFINITY};
    float li[2] = {0.f, 0.f};

    for (int kb = 0; kb < 64; kb++) {
        int cur = kb & 1;
        uint4* Kbuf = (uint4*)(sm + 16384 + cur * BUF_FLOATS);
        uint2* Vbuf = (uint2*)(sm + 16384 + cur * BUF_FLOATS + 8192);

        if (kb < 63) {
            uint4* kd = (uint4*)(sm + 16384 + (1 - cur) * BUF_FLOATS);
            const uint4* ksrc = g_Kpk + ((size_t)(b * 64 + kb + 1)) * 2048;
            for (int i = tid; i < 2048; i += 512) cpasync16(kd + i, ksrc + i);
            uint4* vd = (uint4*)(sm + 16384 + (1 - cur) * BUF_FLOATS + 8192);
            const uint4* vsrc = (const uint4*)(g_Vpk + ((size_t)(b * 64 + kb + 1)) * 2048);
            for (int i = tid; i < 1024; i += 512) cpasync16(vd + i, vsrc + i);
            asm volatile("cp.async.commit_group;\n" ::);
            asm volatile("cp.async.wait_group 1;\n" ::);
        } else {
            asm volatile("cp.async.wait_group 0;\n" ::);
        }
        __syncthreads();

        // ---- S = Q^T K over this group's 32 keys : 3x f16 mma ----
        float S[4][4];
#pragma unroll
        for (int nt = 0; nt < 4; nt++)
#pragma unroll
            for (int j = 0; j < 4; j++) S[nt][j] = 0.f;

#pragma unroll
        for (int ks = 0; ks < 8; ks++) {
            int qi = (ks * 8 + wt) * 32 + lane;
            uint4 qh = Qf[qi];
            uint4 ql = Qf[2048 + qi];
#pragma unroll
            for (int nt4 = 0; nt4 < 4; nt4++) {
                uint4 kf = Kbuf[(ks * 8 + ntb + nt4) * 32 + lane];
                mma_f16(S[nt4], qh.x, qh.y, qh.z, qh.w, kf.x, kf.y);
                mma_f16(S[nt4], ql.x, ql.y, ql.z, ql.w, kf.x, kf.y);
                mma_f16(S[nt4], qh.x, qh.y, qh.z, qh.w, kf.z, kf.w);
            }
        }

        // ---- warp-local online softmax over 32 keys; P overwrites S ----
#pragma unroll
        for (int hb = 0; hb < 2; hb++) {
            float vmax = -INFINITY;
#pragma unroll
            for (int nt = 0; nt < 4; nt++)
                vmax = fmaxf(vmax, fmaxf(S[nt][2 * hb], S[nt][2 * hb + 1]));
            vmax = fmaxf(vmax, __shfl_xor_sync(0xffffffffu, vmax, 1));
            vmax = fmaxf(vmax, __shfl_xor_sync(0xffffffffu, vmax, 2));
            float mnew  = fmaxf(mi[hb], vmax);
            float alpha = exp2f((mi[hb] - mnew) * SCALE2);
            mi[hb] = mnew;

            float rs_ = 0.f;
#pragma unroll
            for (int nt = 0; nt < 4; nt++) {
                float p0 = exp2f((S[nt][2 * hb]     - mnew) * SCALE2);
                float p1 = exp2f((S[nt][2 * hb + 1] - mnew) * SCALE2);
                S[nt][2 * hb]     = p0;
                S[nt][2 * hb + 1] = p1;
                rs_ += p0 + p1;
            }
            rs_ += __shfl_xor_sync(0xffffffffu, rs_, 1);
            rs_ += __shfl_xor_sync(0xffffffffu, rs_, 2);
            li[hb] = li[hb] * alpha + rs_;

#pragma unroll
            for (int ct = 0; ct < 16; ct++) {
                O[ct][2 * hb]     *= alpha;
                O[ct][2 * hb + 1] *= alpha;
            }
        }

        // ---- PV over this group's 2 kt blocks : 2x f16 mma ----
#pragma unroll
        for (int kt2 = 0; kt2 < 2; kt2++) {
            unsigned int Pha[4], Pla[4];
#pragma unroll
            for (int hf2 = 0; hf2 < 2; hf2++) {
                int nt = 2 * kt2 + hf2;
#pragma unroll
                for (int hb = 0; hb < 2; hb++) {
                    float p0 = S[nt][2 * hb], p1 = S[nt][2 * hb + 1];
                    Pha[hf2 * 2 + hb] = pack_hi(p0, p1);
                    Pla[hf2 * 2 + hb] = pack_lo(p0, p1);
                }
            }
            int kt = 2 * grp + kt2;
#pragma unroll
            for (int ct = 0; ct < 16; ct++) {
                uint2 vf = Vbuf[(kt * 16 + ct) * 32 + lane];
                mma_f16(O[ct], Pha[0], Pha[1], Pha[2], Pha[3], vf.x, vf.y);
                mma_f16(O[ct], Pla[0], Pla[1], Pla[2], Pla[3], vf.x, vf.y);
            }
        }
        __syncthreads();
    }

    // ---- cross-group flash merge via smem (aliases buffers) ----
    float* MG = sm + 16384;   // 68 * 512 floats
    if (grp == 1) {
        int slot = tid - 256;
#pragma unroll
        for (int ct = 0; ct < 16; ct++)
#pragma unroll
            for (int j = 0; j < 4; j++)
                MG[(ct * 4 + j) * 512 + slot] = O[ct][j];
#pragma unroll
        for (int hb = 0; hb < 2; hb++) {
            MG[(64 + hb) * 512 + slot] = mi[hb];
            MG[(66 + hb) * 512 + slot] = li[hb];
        }
    }
    __syncthreads();

    if (grp == 0) {
        float* yout = out;
        float* loc  = out + (size_t)BATCH * CH * N_;
#pragma unroll
        for (int hb = 0; hb < 2; hb++) {
            float m1 = MG[(64 + hb) * 512 + tid];
            float l1 = MG[(66 + hb) * 512 + tid];
            float m  = fmaxf(mi[hb], m1);
            float a0 = exp2f((mi[hb] - m) * SCALE2);
            float a1 = exp2f((m1 - m) * SCALE2);
            float lt = li[hb] * a0 + l1 * a1;
            float inv = 1.0f / lt;
            float sc  = m * inv;
            int   r   = n0 + 16 * wt + g + 8 * hb;
#pragma unroll
            for (int ct = 0; ct < 16; ct++) {
                float o0 = O[ct][2 * hb]     * a0 + MG[(ct * 4 + 2 * hb) * 512 + tid]     * a1;
                float o1 = O[ct][2 * hb + 1] * a0 + MG[(ct * 4 + 2 * hb + 1) * 512 + tid] * a1;
                int c0 = 8 * ct + 2 * l;
                yout[((size_t)(b * CH + c0)) * N_ + r]     = o0 * sc;
                yout[((size_t)(b * CH + c0 + 1)) * N_ + r] = o1 * sc;
            }
            if (l == 0) loc[(size_t)b * N_ + r] = inv;
        }
    }
}

// ---------------------------------------------------------------------------
extern "C" void kernel_launch(void* const* d_in, const int* in_sizes, int n_in,
                              void* d_out, int out_size) {
    const float* m_in = (const float*)d_in[0];
    const float* rs   = (const float*)d_in[1];
    const float* thw  = (const float*)d_in[2];
    const float* phw  = (const float*)d_in[4];
    float* out = (float*)d_out;

    k_means<<<1024, 256>>>(m_in, rs);
    k_proj<<<dim3(N_ / 16, BATCH, 2), 128>>>(m_in, rs, thw, phw);

    cudaFuncSetAttribute(k_packQ, cudaFuncAttributeMaxDynamicSharedMemorySize, 132 * 128 * 4);
    k_packQ<<<dim3(32, BATCH), 256, 132 * 128 * 4>>>();
    k_packK<<<dim3(64, BATCH), 256>>>();
    k_packV<<<dim3(64, BATCH), 256>>>(rs);

    size_t smem = (size_t)51200 * sizeof(float);   // 200 KB (merge region aliases buffers)
    cudaFuncSetAttribute(k_attn, cudaFuncAttributeMaxDynamicSharedMemorySize, (int)smem);
    k_attn<<<dim3(N_ / 128, BATCH), 512, smem>>>(out);
}

// round 15
// speedup vs baseline: 1.2637x; 1.1316x over previous
#include <cuda_runtime.h>
#include <cuda_fp16.h>
#include <math.h>

#define BATCH 4
#define CH    128
#define N_    4096
#define EPSV  2.220446049250313e-16f
#define SCALE2 144.26950408889634f   // 100 * log2(e)

// ---------------------------------------------------------------------------
// Device scratch
// ---------------------------------------------------------------------------
__device__ float g_xbar[2 * BATCH * CH];
__device__ float g_theta[BATCH * CH * N_];        // keys    [b][c][m]
__device__ float g_phi[BATCH * CH * N_];          // queries [b][c][n]
__device__ uint4 g_Qpk[BATCH * 32 * 4096];        // Q A-frags: [0,2048) hi, [2048,4096) lo per blk
__device__ uint4 g_Kpk[BATCH * 64 * 2048];        // K B-frags (b0h,b1h,b0l,b1l) per 64-key blk
__device__ uint2 g_Vpk[BATCH * 64 * 2048];        // V B-frags hi-only (vh01,vh89) per blk

__device__ __forceinline__ void mma_f16(float c[4],
                                        unsigned int a0, unsigned int a1,
                                        unsigned int a2, unsigned int a3,
                                        unsigned int b0, unsigned int b1) {
    asm volatile("mma.sync.aligned.m16n8k16.row.col.f32.f16.f16.f32 "
                 "{%0,%1,%2,%3}, {%4,%5,%6,%7}, {%8,%9}, {%0,%1,%2,%3};\n"
                 : "+f"(c[0]), "+f"(c[1]), "+f"(c[2]), "+f"(c[3])
                 : "r"(a0), "r"(a1), "r"(a2), "r"(a3), "r"(b0), "r"(b1));
}

__device__ __forceinline__ unsigned int h2u(__half2 h) {
    return *reinterpret_cast<unsigned int*>(&h);
}

__device__ __forceinline__ unsigned int pack_hi(float a, float b) {
    return h2u(__halves2half2(__float2half_rn(a), __float2half_rn(b)));
}
// lo residual of f16 split
__device__ __forceinline__ unsigned int pack_lo(float a, float b) {
    __half ha = __float2half_rn(a), hb = __float2half_rn(b);
    return h2u(__halves2half2(__float2half_rn(a - __half2float(ha)),
                              __float2half_rn(b - __half2float(hb))));
}

__device__ __forceinline__ void cpasync16(void* s, const void* g) {
    unsigned int saddr = (unsigned int)__cvta_generic_to_shared(s);
    asm volatile("cp.async.cg.shared.global [%0], [%1], 16;\n" :: "r"(saddr), "l"(g));
}

// ---------------------------------------------------------------------------
// K0: spatial means
// ---------------------------------------------------------------------------
__global__ void k_means(const float* __restrict__ m_in, const float* __restrict__ rs) {
    int row   = blockIdx.x;
    int which = row >> 9;
    int bc    = row & 511;
    const float* src = which ? m_in : rs;
    const float* p = src + (size_t)bc * N_;

    float s = 0.f;
    for (int i = threadIdx.x; i < N_; i += 256) s += p[i];

    __shared__ float sh[256];
    sh[threadIdx.x] = s;
    __syncthreads();
    for (int off = 128; off > 0; off >>= 1) {
        if (threadIdx.x < off) sh[threadIdx.x] += sh[threadIdx.x + off];
        __syncthreads();
    }
    if (threadIdx.x == 0) g_xbar[which * 512 + bc] = sh[0] * (1.0f / N_);
}

// ---------------------------------------------------------------------------
// K1: projection + mean-center + L2-normalize (bias cancels under centering)
// ---------------------------------------------------------------------------
__global__ void k_proj(const float* __restrict__ m_in, const float* __restrict__ rs,
                       const float* __restrict__ theta_w, const float* __restrict__ phi_w) {
    int tile  = blockIdx.x;
    int b     = blockIdx.y;
    int which = blockIdx.z;
    const float* X = which ? m_in : rs;
    const float* W = which ? phi_w : theta_w;
    float* OUT     = which ? g_phi : g_theta;
    const float* xbar = &g_xbar[which * 512 + b * CH];

    int o  = threadIdx.x;
    int n0 = tile * 16;

    __shared__ float Ws[128 * 33];
    __shared__ float xs[32 * 16];
    __shared__ float sq[128 * 17];

    float acc[16];
#pragma unroll
    for (int j = 0; j < 16; j++) acc[j] = 0.f;

    for (int c0 = 0; c0 < CH; c0 += 32) {
        for (int i = threadIdx.x; i < 128 * 32; i += 128) {
            int oo = i >> 5, cc = i & 31;
            Ws[oo * 33 + cc] = W[oo * CH + c0 + cc];
        }
        for (int i = threadIdx.x; i < 32 * 16; i += 128) {
            int cc = i >> 4;
            int j  = i & 15;
            int c  = c0 + cc;
            xs[i] = X[((size_t)(b * CH + c)) * N_ + n0 + j] - xbar[c];
        }
        __syncthreads();
#pragma unroll 8
        for (int cc = 0; cc < 32; cc++) {
            float w = Ws[o * 33 + cc];
#pragma unroll
            for (int j = 0; j < 16; j++) acc[j] += w * xs[cc * 16 + j];
        }
        __syncthreads();
    }

#pragma unroll
    for (int j = 0; j < 16; j++) sq[o * 17 + j] = acc[j] * acc[j];
    for (int off = 64; off > 0; off >>= 1) {
        __syncthreads();
        if (o < off) {
#pragma unroll
            for (int j = 0; j < 16; j++) sq[o * 17 + j] += sq[(o + off) * 17 + j];
        }
    }
    __syncthreads();

#pragma unroll
    for (int j = 0; j < 16; j++) {
        float norm = sqrtf(sq[j]) + EPSV;
        OUT[((size_t)(b * CH + o)) * N_ + n0 + j] = acc[j] / norm;
    }
}

// ---------------------------------------------------------------------------
// Pack Q (phi) into m16n8k16 A-frag order, f16 hi + f16 lo.
// ---------------------------------------------------------------------------
__global__ void k_packQ() {
    extern __shared__ float Qs[];   // [c][r] stride 132
    int blk = blockIdx.x, b = blockIdx.y;
    int n0 = blk * 128;

    for (int i = threadIdx.x; i < 16384; i += 256) {
        int c = i >> 7, r = i & 127;
        Qs[c * 132 + r] = g_phi[((size_t)(b * CH + c)) * N_ + n0 + r];
    }
    __syncthreads();

    uint4* dst = g_Qpk + ((size_t)(b * 32 + blk)) * 4096;
    for (int o = threadIdx.x; o < 2048; o += 256) {
        int lane = o & 31, wt = (o >> 5) & 7, ks = o >> 8;
        int g = lane >> 2, l = lane & 3;
        int r = 16 * wt + g, c = 16 * ks + 2 * l;
        float q00 = Qs[c * 132 + r],           q01 = Qs[(c + 1) * 132 + r];
        float q10 = Qs[c * 132 + r + 8],       q11 = Qs[(c + 1) * 132 + r + 8];
        float q20 = Qs[(c + 8) * 132 + r],     q21 = Qs[(c + 9) * 132 + r];
        float q30 = Qs[(c + 8) * 132 + r + 8], q31 = Qs[(c + 9) * 132 + r + 8];
        uint4 hi, lo;
        hi.x = pack_hi(q00, q01); lo.x = pack_lo(q00, q01);
        hi.y = pack_hi(q10, q11); lo.y = pack_lo(q10, q11);
        hi.z = pack_hi(q20, q21); lo.z = pack_lo(q20, q21);
        hi.w = pack_hi(q30, q31); lo.w = pack_lo(q30, q31);
        dst[o] = hi;
        dst[2048 + o] = lo;
    }
}

// ---------------------------------------------------------------------------
// Pack K (theta) into m16n8k16 B-frag order, uint4 = (b0h,b1h,b0l,b1l).
// ---------------------------------------------------------------------------
__global__ void k_packK() {
    __shared__ float Ks[128 * 68];  // [c][m]
    int kb = blockIdx.x, b = blockIdx.y;
    int m0 = kb * 64;

    for (int i = threadIdx.x; i < 8192; i += 256) {
        int c = i >> 6, m = i & 63;
        Ks[c * 68 + m] = g_theta[((size_t)(b * CH + c)) * N_ + m0 + m];
    }
    __syncthreads();

    uint4* dst = g_Kpk + ((size_t)(b * 64 + kb)) * 2048;
    for (int o = threadIdx.x; o < 2048; o += 256) {
        int lane = o & 31, nt = (o >> 5) & 7, ks = o >> 8;
        int g = lane >> 2, l = lane & 3;
        int c = 16 * ks + 2 * l, m = 8 * nt + g;
        float k00 = Ks[c * 68 + m],       k01 = Ks[(c + 1) * 68 + m];
        float k10 = Ks[(c + 8) * 68 + m], k11 = Ks[(c + 9) * 68 + m];
        uint4 outv;
        outv.x = pack_hi(k00, k01);
        outv.y = pack_hi(k10, k11);
        outv.z = pack_lo(k00, k01);
        outv.w = pack_lo(k10, k11);
        dst[o] = outv;
    }
}

// ---------------------------------------------------------------------------
// Pack V (rs) into m16n8k16 B-frag order, f16 hi only (uint2 per frag).
// ---------------------------------------------------------------------------
__global__ void k_packV(const float* __restrict__ rs) {
    __shared__ float Vt[128 * 68];
    int kb = blockIdx.x, b = blockIdx.y;
    int m0 = kb * 64;

    for (int i = threadIdx.x; i < 2048; i += 256) {
        int c = i >> 4, mq = (i & 15) << 2;
        float4 v = *(const float4*)(rs + ((size_t)(b * CH + c)) * N_ + m0 + mq);
        *(float4*)(Vt + c * 68 + mq) = v;
    }
    __syncthreads();

    uint2* dst = g_Vpk + ((size_t)(b * 64 + kb)) * 2048;
    for (int o = threadIdx.x; o < 2048; o += 256) {
        int lane = o & 31, ct = (o >> 5) & 15, kt = o >> 9;
        int g = lane >> 2, l = lane & 3;
        int c = 8 * ct + g;
        int m = 16 * kt + 2 * l;
        uint2 outv;
        outv.x = pack_hi(Vt[c * 68 + m],     Vt[c * 68 + m + 1]);
        outv.y = pack_hi(Vt[c * 68 + m + 8], Vt[c * 68 + m + 9]);
        dst[o] = outv;
    }
}

// ---------------------------------------------------------------------------
// K2: flash attention v8. 512 threads = 16 warps.
// Warp w: wt = w&7 owns rows 16wt..+15; grp = w>>3 owns keys [32*grp, +32).
// S: 3x f16 m16n8k16 (hi/lo). PV: 1x f16 m16n8k16 (Ph*Vh only).
// K/V double-buffered via cp.async. Buffer = K 8192 floats + V 4096 floats.
// ---------------------------------------------------------------------------
#define BUF_FLOATS 12288

__global__ void __launch_bounds__(512, 1)
k_attn(float* __restrict__ out) {
    extern __shared__ float sm[];
    uint4* Qf = (uint4*)sm;                  // 4096 uint4: [0,2048) hi, [2048,4096) lo

    int b    = blockIdx.y;
    int n0   = blockIdx.x << 7;
    int tid  = threadIdx.x;
    int lane = tid & 31, w = tid >> 5;
    int wt = w & 7, grp = w >> 3;
    int ntb = grp << 2;                      // nt base
    int g = lane >> 2, l = lane & 3;

    // load persistent Q fragments
    {
        const uint4* qsrc = g_Qpk + ((size_t)(b * 32 + blockIdx.x)) * 4096;
        for (int i = tid; i < 4096; i += 512) Qf[i] = qsrc[i];
    }

    // prologue: async load tile 0 into buffer 0
    {
        uint4* kd = (uint4*)(sm + 16384);
        const uint4* ksrc = g_Kpk + ((size_t)(b * 64 + 0)) * 2048;
        for (int i = tid; i < 2048; i += 512) cpasync16(kd + i, ksrc + i);
        uint4* vd = (uint4*)(sm + 16384 + 8192);
        const uint4* vsrc = (const uint4*)(g_Vpk + ((size_t)(b * 64 + 0)) * 2048);
        for (int i = tid; i < 1024; i += 512) cpasync16(vd + i, vsrc + i);
        asm volatile("cp.async.commit_group;\n" ::);
    }

    float O[16][4];
#pragma unroll
    for (int ct = 0; ct < 16; ct++)
#pragma unroll
        for (int j = 0; j < 4; j++) O[ct][j] = 0.f;
    float mi[2] = {-INFINITY, -INFINITY};
    float li[2] = {0.f, 0.f};

    for (int kb = 0; kb < 64; kb++) {
        int cur = kb & 1;
        uint4* Kbuf = (uint4*)(sm + 16384 + cur * BUF_FLOATS);
        uint2* Vbuf = (uint2*)(sm + 16384 + cur * BUF_FLOATS + 8192);

        if (kb < 63) {
            uint4* kd = (uint4*)(sm + 16384 + (1 - cur) * BUF_FLOATS);
            const uint4* ksrc = g_Kpk + ((size_t)(b * 64 + kb + 1)) * 2048;
            for (int i = tid; i < 2048; i += 512) cpasync16(kd + i, ksrc + i);
            uint4* vd = (uint4*)(sm + 16384 + (1 - cur) * BUF_FLOATS + 8192);
            const uint4* vsrc = (const uint4*)(g_Vpk + ((size_t)(b * 64 + kb + 1)) * 2048);
            for (int i = tid; i < 1024; i += 512) cpasync16(vd + i, vsrc + i);
            asm volatile("cp.async.commit_group;\n" ::);
            asm volatile("cp.async.wait_group 1;\n" ::);
        } else {
            asm volatile("cp.async.wait_group 0;\n" ::);
        }
        __syncthreads();

        // ---- S = Q^T K over this group's 32 keys : 3x f16 mma ----
        float S[4][4];
#pragma unroll
        for (int nt = 0; nt < 4; nt++)
#pragma unroll
            for (int j = 0; j < 4; j++) S[nt][j] = 0.f;

#pragma unroll
        for (int ks = 0; ks < 8; ks++) {
            int qi = (ks * 8 + wt) * 32 + lane;
            uint4 qh = Qf[qi];
            uint4 ql = Qf[2048 + qi];
#pragma unroll
            for (int nt4 = 0; nt4 < 4; nt4++) {
                uint4 kf = Kbuf[(ks * 8 + ntb + nt4) * 32 + lane];
                mma_f16(S[nt4], qh.x, qh.y, qh.z, qh.w, kf.x, kf.y);
                mma_f16(S[nt4], ql.x, ql.y, ql.z, ql.w, kf.x, kf.y);
                mma_f16(S[nt4], qh.x, qh.y, qh.z, qh.w, kf.z, kf.w);
            }
        }

        // ---- warp-local online softmax over 32 keys; P overwrites S ----
#pragma unroll
        for (int hb = 0; hb < 2; hb++) {
            float vmax = -INFINITY;
#pragma unroll
            for (int nt = 0; nt < 4; nt++)
                vmax = fmaxf(vmax, fmaxf(S[nt][2 * hb], S[nt][2 * hb + 1]));
            vmax = fmaxf(vmax, __shfl_xor_sync(0xffffffffu, vmax, 1));
            vmax = fmaxf(vmax, __shfl_xor_sync(0xffffffffu, vmax, 2));
            float mnew  = fmaxf(mi[hb], vmax);
            float alpha = exp2f((mi[hb] - mnew) * SCALE2);
            mi[hb] = mnew;

            float rs_ = 0.f;
#pragma unroll
            for (int nt = 0; nt < 4; nt++) {
                float p0 = exp2f((S[nt][2 * hb]     - mnew) * SCALE2);
                float p1 = exp2f((S[nt][2 * hb + 1] - mnew) * SCALE2);
                S[nt][2 * hb]     = p0;
                S[nt][2 * hb + 1] = p1;
                rs_ += p0 + p1;
            }
            rs_ += __shfl_xor_sync(0xffffffffu, rs_, 1);
            rs_ += __shfl_xor_sync(0xffffffffu, rs_, 2);
            li[hb] = li[hb] * alpha + rs_;

#pragma unroll
            for (int ct = 0; ct < 16; ct++) {
                O[ct][2 * hb]     *= alpha;
                O[ct][2 * hb + 1] *= alpha;
            }
        }

        // ---- PV over this group's 2 kt blocks : 1x f16 mma (Ph*Vh) ----
#pragma unroll
        for (int kt2 = 0; kt2 < 2; kt2++) {
            unsigned int Pha[4];
#pragma unroll
            for (int hf2 = 0; hf2 < 2; hf2++) {
                int nt = 2 * kt2 + hf2;
#pragma unroll
                for (int hb = 0; hb < 2; hb++)
                    Pha[hf2 * 2 + hb] = pack_hi(S[nt][2 * hb], S[nt][2 * hb + 1]);
            }
            int kt = 2 * grp + kt2;
#pragma unroll
            for (int ct = 0; ct < 16; ct++) {
                uint2 vf = Vbuf[(kt * 16 + ct) * 32 + lane];
                mma_f16(O[ct], Pha[0], Pha[1], Pha[2], Pha[3], vf.x, vf.y);
            }
        }
        __syncthreads();
    }

    // ---- cross-group flash merge via smem (aliases buffers) ----
    float* MG = sm + 16384;   // 68 * 512 floats
    if (grp == 1) {
        int slot = tid - 256;
#pragma unroll
        for (int ct = 0; ct < 16; ct++)
#pragma unroll
            for (int j = 0; j < 4; j++)
                MG[(ct * 4 + j) * 512 + slot] = O[ct][j];
#pragma unroll
        for (int hb = 0; hb < 2; hb++) {
            MG[(64 + hb) * 512 + slot] = mi[hb];
            MG[(66 + hb) * 512 + slot] = li[hb];
        }
    }
    __syncthreads();

    if (grp == 0) {
        float* yout = out;
        float* loc  = out + (size_t)BATCH * CH * N_;
#pragma unroll
        for (int hb = 0; hb < 2; hb++) {
            float m1 = MG[(64 + hb) * 512 + tid];
            float l1 = MG[(66 + hb) * 512 + tid];
            float m  = fmaxf(mi[hb], m1);
            float a0 = exp2f((mi[hb] - m) * SCALE2);
            float a1 = exp2f((m1 - m) * SCALE2);
            float lt = li[hb] * a0 + l1 * a1;
            float inv = 1.0f / lt;
            float sc  = m * inv;
            int   r   = n0 + 16 * wt + g + 8 * hb;
#pragma unroll
            for (int ct = 0; ct < 16; ct++) {
                float o0 = O[ct][2 * hb]     * a0 + MG[(ct * 4 + 2 * hb) * 512 + tid]     * a1;
                float o1 = O[ct][2 * hb + 1] * a0 + MG[(ct * 4 + 2 * hb + 1) * 512 + tid] * a1;
                int c0 = 8 * ct + 2 * l;
                yout[((size_t)(b * CH + c0)) * N_ + r]     = o0 * sc;
                yout[((size_t)(b * CH + c0 + 1)) * N_ + r] = o1 * sc;
            }
            if (l == 0) loc[(size_t)b * N_ + r] = inv;
        }
    }
}

// ---------------------------------------------------------------------------
extern "C" void kernel_launch(void* const* d_in, const int* in_sizes, int n_in,
                              void* d_out, int out_size) {
    const float* m_in = (const float*)d_in[0];
    const float* rs   = (const float*)d_in[1];
    const float* thw  = (const float*)d_in[2];
    const float* phw  = (const float*)d_in[4];
    float* out = (float*)d_out;

    k_means<<<1024, 256>>>(m_in, rs);
    k_proj<<<dim3(N_ / 16, BATCH, 2), 128>>>(m_in, rs, thw, phw);

    cudaFuncSetAttribute(k_packQ, cudaFuncAttributeMaxDynamicSharedMemorySize, 132 * 128 * 4);
    k_packQ<<<dim3(32, BATCH), 256, 132 * 128 * 4>>>();
    k_packK<<<dim3(64, BATCH), 256>>>();
    k_packV<<<dim3(64, BATCH), 256>>>(rs);

    size_t smem = (size_t)51200 * sizeof(float);   // 200 KB (merge region aliases buffers)
    cudaFuncSetAttribute(k_attn, cudaFuncAttributeMaxDynamicSharedMemorySize, (int)smem);
    k_attn<<<dim3(N_ / 128, BATCH), 512, smem>>>(out);
}